// round 1
// baseline (speedup 1.0000x reference)
#include <cuda_runtime.h>
#include <math.h>

#define B_DIM 32
#define S_DIM 128
#define E_DIM 512
#define F_DIM 2048
#define LN_EPS 1e-5f

// 32MB scratch for h = x@W1 + b1   (device global: allocation-guard-safe)
__device__ float g_h[(size_t)B_DIM * S_DIM * F_DIM];

// ---------------- cp.async helpers ----------------
__device__ __forceinline__ void cp_async16(void* smem, const void* gmem) {
    unsigned s = (unsigned)__cvta_generic_to_shared(smem);
    asm volatile("cp.async.cg.shared.global [%0], [%1], 16;\n" :: "r"(s), "l"(gmem));
}
__device__ __forceinline__ void cp_async4(void* smem, const void* gmem) {
    unsigned s = (unsigned)__cvta_generic_to_shared(smem);
    asm volatile("cp.async.ca.shared.global [%0], [%1], 4;\n" :: "r"(s), "l"(gmem));
}
__device__ __forceinline__ void cp_commit() { asm volatile("cp.async.commit_group;\n"); }
__device__ __forceinline__ void cp_wait0() { asm volatile("cp.async.wait_group 0;\n"); }

// ----------------------------------------------------------------------------
// Batched-per-s GEMM:  C[b, s, n0..n0+127] = sum_k A[b, s, k] * W[s, k, n] + bias[s, n]
//                      (+ res[b, s, n] if RES)
// A layout: [B, S, K]   W layout: [S, K, N]   C/res: [B, S, N]   bias: [S, N]
// Grid: (N/128, S).  Block: 128 threads.  Microtile: 4 rows(b) x 8 cols(n).
// ----------------------------------------------------------------------------
template<int K_TOT, int N_TOT, bool A_IS_H, bool C_IS_H, bool RES>
__global__ __launch_bounds__(128, 4)
void ffn_gemm(const float* __restrict__ Ag, const float* __restrict__ W,
              const float* __restrict__ bias, const float* __restrict__ res,
              float* __restrict__ Cg)
{
    constexpr int KT = 32;
    constexpr int NT = 128;
    constexpr int NK = K_TOT / KT;

    const int s   = blockIdx.y;
    const int n0  = blockIdx.x * NT;
    const int tid = threadIdx.x;
    const int ty  = tid >> 4;   // 0..7  -> rows ty*4 .. ty*4+3
    const int tx  = tid & 15;   // 0..15 -> cols tx*8 .. tx*8+7
    const int r0  = ty * 4;
    const int c0  = tx * 8;

    __shared__ float As[2][32][KT + 1];     // [b][k], padded (+1) for conflict-free reads
    __shared__ float Bs[2][KT][NT];         // [k][n]

    const float* A = A_IS_H ? (const float*)g_h : Ag;
    float*       C = C_IS_H ? (float*)g_h       : Cg;

    const float* Aptr = A + (size_t)s * K_TOT;                       // + b*S*K + k
    const float* Wptr = W + (size_t)s * K_TOT * N_TOT + n0;          // + k*N + n

    // ---- tile loader ----
    auto load_tile = [&](int kt, int bf) {
        const int k0 = kt * KT;
        // A tile: 32 x 32 floats, 4B cp.async, coalesced over kk
        #pragma unroll
        for (int p = 0; p < 8; p++) {
            int i  = p * 128 + tid;
            int bb = i >> 5;
            int kk = i & 31;
            cp_async4(&As[bf][bb][kk],
                      Aptr + (size_t)bb * (S_DIM * K_TOT) + k0 + kk);
        }
        // B tile: 32 x 128 floats, 16B cp.async, coalesced over n
        #pragma unroll
        for (int p = 0; p < 8; p++) {
            int i  = p * 128 + tid;
            int rr = i >> 5;
            int c4 = (i & 31) * 4;
            cp_async16(&Bs[bf][rr][c4], Wptr + (size_t)(k0 + rr) * N_TOT + c4);
        }
    };

    float acc[4][8];
    #pragma unroll
    for (int i = 0; i < 4; i++)
        #pragma unroll
        for (int j = 0; j < 8; j++) acc[i][j] = 0.f;

    load_tile(0, 0);
    cp_commit();

    int buf = 0;
    for (int kt = 0; kt < NK; kt++) {
        cp_wait0();
        __syncthreads();                 // tile 'buf' ready; prev compute done
        if (kt + 1 < NK) { load_tile(kt + 1, buf ^ 1); cp_commit(); }

        #pragma unroll
        for (int kk = 0; kk < KT; kk++) {
            float a_[4];
            #pragma unroll
            for (int i = 0; i < 4; i++) a_[i] = As[buf][r0 + i][kk];
            float4 b0 = *(const float4*)&Bs[buf][kk][c0];
            float4 b1v = *(const float4*)&Bs[buf][kk][c0 + 4];
            #pragma unroll
            for (int i = 0; i < 4; i++) {
                acc[i][0] = fmaf(a_[i], b0.x,  acc[i][0]);
                acc[i][1] = fmaf(a_[i], b0.y,  acc[i][1]);
                acc[i][2] = fmaf(a_[i], b0.z,  acc[i][2]);
                acc[i][3] = fmaf(a_[i], b0.w,  acc[i][3]);
                acc[i][4] = fmaf(a_[i], b1v.x, acc[i][4]);
                acc[i][5] = fmaf(a_[i], b1v.y, acc[i][5]);
                acc[i][6] = fmaf(a_[i], b1v.z, acc[i][6]);
                acc[i][7] = fmaf(a_[i], b1v.w, acc[i][7]);
            }
        }
        buf ^= 1;
    }

    // ---- epilogue: bias (+ residual) ----
    const float* bp = bias + (size_t)s * N_TOT + n0 + c0;
    float bv[8];
    #pragma unroll
    for (int j = 0; j < 8; j++) bv[j] = bp[j];

    #pragma unroll
    for (int i = 0; i < 4; i++) {
        const size_t off = ((size_t)(r0 + i) * S_DIM + s) * N_TOT + n0 + c0;
        float o[8];
        if (RES) {
            const float* rp = res + off;
            #pragma unroll
            for (int j = 0; j < 8; j++) o[j] = acc[i][j] + bv[j] + rp[j];
        } else {
            #pragma unroll
            for (int j = 0; j < 8; j++) o[j] = acc[i][j] + bv[j];
        }
        float4* cp4 = (float4*)(C + off);
        cp4[0] = make_float4(o[0], o[1], o[2], o[3]);
        cp4[1] = make_float4(o[4], o[5], o[6], o[7]);
    }
}

// ----------------------------------------------------------------------------
// LayerNorm over last dim (E=512), in-place on d_out. One block per (b,s) row.
// ----------------------------------------------------------------------------
__global__ __launch_bounds__(256)
void ln_kernel(float* __restrict__ y,
               const float* __restrict__ gamma, const float* __restrict__ beta)
{
    const int row = blockIdx.x;                 // b*S + s
    float* p = y + (size_t)row * E_DIM;
    const int t = threadIdx.x;                  // 0..255, 2 elems each

    float2 v = *(const float2*)&p[t * 2];
    float sum = v.x + v.y;
    float sq  = v.x * v.x + v.y * v.y;

    // warp reduce
    #pragma unroll
    for (int o = 16; o > 0; o >>= 1) {
        sum += __shfl_down_sync(0xffffffffu, sum, o);
        sq  += __shfl_down_sync(0xffffffffu, sq,  o);
    }
    __shared__ float s_sum[8], s_sq[8];
    const int wid = t >> 5, lid = t & 31;
    if (lid == 0) { s_sum[wid] = sum; s_sq[wid] = sq; }
    __syncthreads();

    __shared__ float s_mu, s_inv;
    if (t == 0) {
        float ts = 0.f, tq = 0.f;
        #pragma unroll
        for (int i = 0; i < 8; i++) { ts += s_sum[i]; tq += s_sq[i]; }
        float mu  = ts * (1.0f / E_DIM);
        float var = tq * (1.0f / E_DIM) - mu * mu;
        s_mu  = mu;
        s_inv = rsqrtf(var + LN_EPS);
    }
    __syncthreads();

    const float mu = s_mu, inv = s_inv;
    float2 g = *(const float2*)&gamma[t * 2];
    float2 b = *(const float2*)&beta[t * 2];
    v.x = (v.x - mu) * inv * g.x + b.x;
    v.y = (v.y - mu) * inv * g.y + b.y;
    *(float2*)&p[t * 2] = v;
}

// ----------------------------------------------------------------------------
extern "C" void kernel_launch(void* const* d_in, const int* in_sizes, int n_in,
                              void* d_out, int out_size)
{
    const float* x     = (const float*)d_in[0];
    const float* W1    = (const float*)d_in[1];
    const float* b1    = (const float*)d_in[2];
    const float* W2    = (const float*)d_in[3];
    const float* b2    = (const float*)d_in[4];
    const float* gamma = (const float*)d_in[5];
    const float* beta  = (const float*)d_in[6];
    float* out = (float*)d_out;

    // GEMM1: h = x @ W1 + b1     (K=E=512, N=F=2048) -> g_h
    {
        dim3 grid(F_DIM / 128, S_DIM);
        ffn_gemm<E_DIM, F_DIM, /*A_IS_H=*/false, /*C_IS_H=*/true, /*RES=*/false>
            <<<grid, 128>>>(x, W1, b1, nullptr, nullptr);
    }
    // GEMM2: y = h @ W2 + b2 + x (K=F=2048, N=E=512) -> d_out
    {
        dim3 grid(E_DIM / 128, S_DIM);
        ffn_gemm<F_DIM, E_DIM, /*A_IS_H=*/true, /*C_IS_H=*/false, /*RES=*/true>
            <<<grid, 128>>>(nullptr, W2, b2, x, out);
    }
    // LayerNorm in-place on d_out
    ln_kernel<<<B_DIM * S_DIM, 256>>>(out, gamma, beta);
}